// round 8
// baseline (speedup 1.0000x reference)
#include <cuda_runtime.h>
#include <cuda_bf16.h>
#include <cstdint>
#include <cstddef>

#define T_TOK 2048
#define HDIM  1024
#define EDIM  64
#define NTOPK 8
#define IDIM  512

#define NSLOTS (T_TOK * NTOPK)      // 16384
#define PADSLOTS (NSLOTS + 128)

#define BM 128
#define BN 128
#define KC 64

// per-stage smem layout (bytes)
#define STG_A_HI 0                   // 128 x 64 bf16 = 16384
#define STG_A_LO 16384
#define STG_B    32768               // 64 x 128 bf16 = 16384
#define STG_SIZE 49152
#define OFF_TOKS 98304               // 128 ints
#define OFF_TWS  98816               // 128 floats
#define OFF_SC   99328               // up to 1024 floats
#define SMEM_TOTAL 103424

typedef unsigned int u32;

// ---------------- device scratch ----------------
__device__ int   g_count[EDIM];
__device__ int   g_offset[EDIM + 1];
__device__ int   g_fill[EDIM];
__device__ int   g_topk_idx[NSLOTS];
__device__ float g_topk_w[NSLOTS];
__device__ int   g_tok[PADSLOTS];
__device__ float g_tw[PADSLOTS];
__device__ __nv_bfloat16 g_xhi[(size_t)T_TOK * HDIM];
__device__ __nv_bfloat16 g_xlo[(size_t)T_TOK * HDIM];
__device__ __nv_bfloat16 g_hh[(size_t)PADSLOTS * IDIM];
__device__ __nv_bfloat16 g_hl[(size_t)PADSLOTS * IDIM];
__device__ __nv_bfloat16 g_w1deq[(size_t)HDIM * (EDIM * IDIM)];   // 64 MB
__device__ __nv_bfloat16 g_w2deq[(size_t)IDIM * (EDIM * HDIM)];   // 64 MB

__device__ __forceinline__ float silu_f(float v) { return v / (1.0f + __expf(-v)); }

__device__ __forceinline__ u32 smem_u32(const void* p) {
    u32 a;
    asm("{ .reg .u64 t; cvta.to.shared.u64 t, %1; cvt.u32.u64 %0, t; }" : "=r"(a) : "l"(p));
    return a;
}

__device__ __forceinline__ void cp_async16(u32 dst, const void* src) {
    asm volatile("cp.async.cg.shared.global [%0], [%1], 16;" :: "r"(dst), "l"(src));
}
#define CP_COMMIT() asm volatile("cp.async.commit_group;" ::: "memory")
#define CP_WAIT(n)  asm volatile("cp.async.wait_group %0;" :: "n"(n) : "memory")

#define LDMX4(r0, r1, r2, r3, addr) \
    asm volatile("ldmatrix.sync.aligned.m8n8.x4.shared.b16 {%0,%1,%2,%3}, [%4];" \
                 : "=r"(r0), "=r"(r1), "=r"(r2), "=r"(r3) : "r"(addr))

#define LDMX4T(r0, r1, r2, r3, addr) \
    asm volatile("ldmatrix.sync.aligned.m8n8.x4.trans.shared.b16 {%0,%1,%2,%3}, [%4];" \
                 : "=r"(r0), "=r"(r1), "=r"(r2), "=r"(r3) : "r"(addr))

#define MMA16816(d, a0, a1, a2, a3, b0, b1) \
    asm volatile("mma.sync.aligned.m16n8k16.row.col.f32.bf16.bf16.f32 " \
                 "{%0,%1,%2,%3}, {%4,%5,%6,%7}, {%8,%9}, {%0,%1,%2,%3};" \
                 : "+f"((d)[0]), "+f"((d)[1]), "+f"((d)[2]), "+f"((d)[3]) \
                 : "r"(a0), "r"(a1), "r"(a2), "r"(a3), "r"(b0), "r"(b1))

// ---------------- pre-processing kernels ----------------
__global__ __launch_bounds__(256) void dequant_kernel(const int* __restrict__ qw,
                                                      const int* __restrict__ qz,
                                                      int ncol8, int which) {
    __nv_bfloat16* __restrict__ wdeq = which ? g_w2deq : g_w1deq;
    int idx = blockIdx.x * 256 + threadIdx.x;
    int k = idx / ncol8, c8 = idx - k * ncol8;
    unsigned qv = (unsigned)qw[idx];
    unsigned zv = (unsigned)qz[(k >> 7) * ncol8 + c8];
    const int sh[8] = {0, 16, 4, 20, 8, 24, 12, 28};
    u32 o[4];
#pragma unroll
    for (int j = 0; j < 4; j++) {
        int d0 = (int)((qv >> sh[2 * j])     & 0xF) - (int)((zv >> sh[2 * j])     & 0xF);
        int d1 = (int)((qv >> sh[2 * j + 1]) & 0xF) - (int)((zv >> sh[2 * j + 1]) & 0xF);
        __nv_bfloat162 p = __floats2bfloat162_rn((float)d0, (float)d1);
        o[j] = *(u32*)&p;
    }
    *(uint4*)(wdeq + (size_t)idx * 8) = make_uint4(o[0], o[1], o[2], o[3]);
}

__global__ __launch_bounds__(256) void xsplit_kernel(const float* __restrict__ x) {
    int i = blockIdx.x * 256 + threadIdx.x;
    float4 v = *(const float4*)(x + (size_t)i * 4);
    __nv_bfloat162 h01 = __floats2bfloat162_rn(v.x, v.y);
    __nv_bfloat162 h23 = __floats2bfloat162_rn(v.z, v.w);
    float lx = v.x - __bfloat162float(__low2bfloat16(h01));
    float ly = v.y - __bfloat162float(__high2bfloat16(h01));
    float lz = v.z - __bfloat162float(__low2bfloat16(h23));
    float lw = v.w - __bfloat162float(__high2bfloat16(h23));
    __nv_bfloat162 l01 = __floats2bfloat162_rn(lx, ly);
    __nv_bfloat162 l23 = __floats2bfloat162_rn(lz, lw);
    *(uint2*)(g_xhi + (size_t)i * 4) = make_uint2(*(u32*)&h01, *(u32*)&h23);
    *(uint2*)(g_xlo + (size_t)i * 4) = make_uint2(*(u32*)&l01, *(u32*)&l23);
}

// ---------------- routing kernels ----------------
__global__ void init_kernel() {
    int i = threadIdx.x;
    if (i < EDIM) g_count[i] = 0;
}

__global__ __launch_bounds__(256) void route_kernel(const float* __restrict__ x,
                                                    const float* __restrict__ gw) {
    int t = blockIdx.x;
    __shared__ float xs[HDIM];
    __shared__ float part[256];
    __shared__ float logit[EDIM];
    int tid = threadIdx.x;
    for (int i = tid; i < HDIM; i += 256) xs[i] = x[t * HDIM + i];
    __syncthreads();
    int e = tid & 63, q = tid >> 6;
    const float* w  = gw + e * HDIM + q * 256;
    const float* xq = xs + q * 256;
    float s = 0.f;
#pragma unroll 8
    for (int i = 0; i < 256; i++) s += xq[i] * w[i];
    part[tid] = s;
    __syncthreads();
    if (tid < 64)
        logit[tid] = part[tid] + part[tid + 64] + part[tid + 128] + part[tid + 192];
    __syncthreads();
    if (tid == 0) {
        float lv[NTOPK]; int li[NTOPK];
        for (int k = 0; k < NTOPK; k++) {
            float best = -1e30f; int bi = 0;
            for (int i = 0; i < EDIM; i++) { float v = logit[i]; if (v > best) { best = v; bi = i; } }
            lv[k] = best; li[k] = bi; logit[bi] = -1e30f;
        }
        float m = lv[0], sum = 0.f, wv[NTOPK];
        for (int k = 0; k < NTOPK; k++) { wv[k] = __expf(lv[k] - m); sum += wv[k]; }
        float inv = 1.f / sum;
        for (int k = 0; k < NTOPK; k++) {
            g_topk_idx[t * NTOPK + k] = li[k];
            g_topk_w[t * NTOPK + k]   = wv[k] * inv;
            atomicAdd(&g_count[li[k]], 1);
        }
    }
}

__global__ void prefix_kernel() {
    if (threadIdx.x == 0) {
        int acc = 0;
        for (int e = 0; e < EDIM; e++) { g_offset[e] = acc; acc += g_count[e]; g_fill[e] = 0; }
        g_offset[EDIM] = acc;
    }
}

__global__ void fill_kernel() {
    int i = blockIdx.x * blockDim.x + threadIdx.x;
    if (i >= NSLOTS) return;
    int e = g_topk_idx[i];
    int slot = atomicAdd(&g_fill[e], 1);
    int pos = g_offset[e] + slot;
    g_tok[pos] = i / NTOPK;
    g_tw[pos]  = g_topk_w[i];
}

// ---------------- warp MMA over one KC=64 stage (warp tile 64x32) ----------------
__device__ __forceinline__ void warp_mma_chunk(u32 sb, int warp_m, int warp_n,
                                               int lane, float accg[4][4][4]) {
#pragma unroll
    for (int ks = 0; ks < 4; ks++) {
        u32 b[4][2];
#pragma unroll
        for (int h = 0; h < 2; h++) {
            int tile = lane >> 3, row = lane & 7;
            int kk = ks * 16 + (tile & 1) * 8 + row;
            int nn = warp_n * 32 + h * 16 + (tile >> 1) * 8;
            u32 addr = sb + STG_B + (u32)(kk * 256 + (((nn >> 3) ^ (kk & 7)) << 4));
            LDMX4T(b[h * 2][0], b[h * 2][1], b[h * 2 + 1][0], b[h * 2 + 1][1], addr);
        }
#pragma unroll
        for (int p = 0; p < 2; p++) {
            const u32 abase = sb + (p ? STG_A_LO : STG_A_HI);
#pragma unroll
            for (int mf = 0; mf < 4; mf++) {
                int mm = warp_m * 64 + mf * 16 + (lane & 15);
                int ch = ks * 2 + (lane >> 4);
                u32 addr = abase + (u32)(mm * 128 + ((ch ^ (mm & 7)) << 4));
                u32 a0, a1, a2, a3;
                LDMX4(a0, a1, a2, a3, addr);
                MMA16816(accg[mf][0], a0, a1, a2, a3, b[0][0], b[0][1]);
                MMA16816(accg[mf][1], a0, a1, a2, a3, b[1][0], b[1][1]);
                MMA16816(accg[mf][2], a0, a1, a2, a3, b[2][0], b[2][1]);
                MMA16816(accg[mf][3], a0, a1, a2, a3, b[3][0], b[3][1]);
            }
        }
    }
}

__device__ __forceinline__ void fold_group(float accg[4][4][4], float accf[4][4][4],
                                           const float* sc_g, int warp_n, int lane) {
#pragma unroll
    for (int nf = 0; nf < 4; nf++) {
        int col = warp_n * 32 + nf * 8 + (lane & 3) * 2;
        float s0 = sc_g[col], s1 = sc_g[col + 1];
#pragma unroll
        for (int mf = 0; mf < 4; mf++) {
            accf[mf][nf][0] += s0 * accg[mf][nf][0];
            accf[mf][nf][1] += s1 * accg[mf][nf][1];
            accf[mf][nf][2] += s0 * accg[mf][nf][2];
            accf[mf][nf][3] += s1 * accg[mf][nf][3];
            accg[mf][nf][0] = 0.f; accg[mf][nf][1] = 0.f;
            accg[mf][nf][2] = 0.f; accg[mf][nf][3] = 0.f;
        }
    }
}

// ---------------- GEMM1 ----------------
__global__ __launch_bounds__(256, 1) void gemm1_kernel(const float* __restrict__ sc1) {
    const int e    = blockIdx.z;
    const int base = g_offset[e];
    const int cnt  = g_offset[e + 1] - base;
    const int m0   = blockIdx.y * BM;
    if (m0 >= cnt) return;
    const int i0 = blockIdx.x * BN;

    extern __shared__ char sm[];
    const u32 smb = smem_u32(sm);
    int*   toks_sm = (int*)(sm + OFF_TOKS);
    float* tws_sm  = (float*)(sm + OFF_TWS);
    float* sc_sm   = (float*)(sm + OFF_SC);

    const int tid  = threadIdx.x;
    const int wid  = tid >> 5;
    const int lane = tid & 31;
    const int warp_m = wid & 1;
    const int warp_n = wid >> 1;

    if (tid < 128) {
        toks_sm[tid] = g_tok[base + m0 + tid];
        tws_sm[tid]  = g_tw[base + m0 + tid];
    }
#pragma unroll
    for (int it = 0; it < 4; it++) {       // 8 groups x 128 cols
        int idx = it * 256 + tid;
        sc_sm[idx] = sc1[(idx >> 7) * 32768 + e * IDIM + i0 + (idx & 127)];
    }
    __syncthreads();

    // loader setup: A 8 cp/thread, B 4 cp/thread
    const __nv_bfloat16* a_hi[4];
    const __nv_bfloat16* a_lo[4];
    u32 a_dst[4];
#pragma unroll
    for (int it = 0; it < 4; it++) {
        int idx = it * 256 + tid;
        int m = idx >> 3, cc = idx & 7;
        size_t rb = (size_t)toks_sm[m] * HDIM + cc * 8;
        a_hi[it] = g_xhi + rb;
        a_lo[it] = g_xlo + rb;
        a_dst[it] = (u32)(m * 128 + ((cc ^ (m & 7)) << 4));
    }
    u32 b_dst[4]; size_t b_src[4];
    const int ncolbase = e * IDIM + i0;
#pragma unroll
    for (int it = 0; it < 4; it++) {
        int idx = it * 256 + tid;            // 0..1023
        int kr = idx >> 4, cc = idx & 15;    // 64 rows x 16 chunks16B
        b_dst[it] = (u32)(STG_B + kr * 256 + ((cc ^ (kr & 7)) << 4));
        b_src[it] = (size_t)kr * 32768 + ncolbase + cc * 8;
    }

    auto load_stage = [&](int c) {
        u32 sb = smb + (c & 1) * STG_SIZE;
        const int k0 = c * KC;
#pragma unroll
        for (int it = 0; it < 4; it++) {
            cp_async16(sb + STG_A_HI + a_dst[it], a_hi[it] + k0);
            cp_async16(sb + STG_A_LO + a_dst[it], a_lo[it] + k0);
        }
        const __nv_bfloat16* wb = g_w1deq + (size_t)k0 * 32768;
#pragma unroll
        for (int it = 0; it < 4; it++)
            cp_async16(sb + b_dst[it], wb + b_src[it]);
    };

    float accg[4][4][4], accf[4][4][4];
#pragma unroll
    for (int a = 0; a < 4; a++)
#pragma unroll
        for (int b = 0; b < 4; b++)
#pragma unroll
            for (int c = 0; c < 4; c++) { accg[a][b][c] = 0.f; accf[a][b][c] = 0.f; }

    const int NCH = HDIM / KC;  // 16
    load_stage(0); CP_COMMIT();
#pragma unroll 1
    for (int c = 0; c < NCH; c++) {
        CP_WAIT(0);
        __syncthreads();
        if (c + 1 < NCH) { load_stage(c + 1); CP_COMMIT(); }
        warp_mma_chunk(smb + (c & 1) * STG_SIZE, warp_m, warp_n, lane, accg);
        if (c & 1) fold_group(accg, accf, sc_sm + (c >> 1) * 128, warp_n, lane);
    }

    // epilogue: silu * tw -> bf16 hi/lo pair
#pragma unroll
    for (int mf = 0; mf < 4; mf++) {
#pragma unroll
        for (int dd = 0; dd < 2; dd++) {
            int ml = warp_m * 64 + mf * 16 + (lane >> 2) + dd * 8;
            int gm = m0 + ml;
            if (gm < cnt) {
                float tw = tws_sm[ml];
                __nv_bfloat16* oph = g_hh + (size_t)(base + gm) * IDIM + i0;
                __nv_bfloat16* opl = g_hl + (size_t)(base + gm) * IDIM + i0;
#pragma unroll
                for (int nf = 0; nf < 4; nf++) {
                    int col = warp_n * 32 + nf * 8 + (lane & 3) * 2;
                    float v0 = silu_f(accf[mf][nf][dd * 2]) * tw;
                    float v1 = silu_f(accf[mf][nf][dd * 2 + 1]) * tw;
                    __nv_bfloat162 h = __floats2bfloat162_rn(v0, v1);
                    float l0 = v0 - __bfloat162float(__low2bfloat16(h));
                    float l1 = v1 - __bfloat162float(__high2bfloat16(h));
                    __nv_bfloat162 l = __floats2bfloat162_rn(l0, l1);
                    *(u32*)(oph + col) = *(u32*)&h;
                    *(u32*)(opl + col) = *(u32*)&l;
                }
            }
        }
    }
}

// ---------------- GEMM2 ----------------
__global__ __launch_bounds__(256, 1) void gemm2_kernel(const float* __restrict__ sc2,
                                                       float* __restrict__ out) {
    const int e    = blockIdx.z;
    const int base = g_offset[e];
    const int cnt  = g_offset[e + 1] - base;
    const int m0   = blockIdx.y * BM;
    if (m0 >= cnt) return;
    const int h0 = blockIdx.x * BN;

    extern __shared__ char sm[];
    const u32 smb = smem_u32(sm);
    int*   toks_sm = (int*)(sm + OFF_TOKS);
    float* sc_sm   = (float*)(sm + OFF_SC);

    const int tid  = threadIdx.x;
    const int wid  = tid >> 5;
    const int lane = tid & 31;
    const int warp_m = wid & 1;
    const int warp_n = wid >> 1;

    if (tid < 128) toks_sm[tid] = g_tok[base + m0 + tid];
#pragma unroll
    for (int it = 0; it < 2; it++) {       // 4 groups x 128 cols
        int idx = it * 256 + tid;
        sc_sm[idx] = sc2[(idx >> 7) * 65536 + e * HDIM + h0 + (idx & 127)];
    }
    __syncthreads();

    const __nv_bfloat16* a_hi[4];
    const __nv_bfloat16* a_lo[4];
    u32 a_dst[4];
#pragma unroll
    for (int it = 0; it < 4; it++) {
        int idx = it * 256 + tid;
        int m = idx >> 3, cc = idx & 7;
        size_t rb = (size_t)(base + m0 + m) * IDIM + cc * 8;
        a_hi[it] = g_hh + rb;
        a_lo[it] = g_hl + rb;
        a_dst[it] = (u32)(m * 128 + ((cc ^ (m & 7)) << 4));
    }
    u32 b_dst[4]; size_t b_src[4];
    const int ncolbase = e * HDIM + h0;
#pragma unroll
    for (int it = 0; it < 4; it++) {
        int idx = it * 256 + tid;
        int kr = idx >> 4, cc = idx & 15;
        b_dst[it] = (u32)(STG_B + kr * 256 + ((cc ^ (kr & 7)) << 4));
        b_src[it] = (size_t)kr * 65536 + ncolbase + cc * 8;
    }

    auto load_stage = [&](int c) {
        u32 sb = smb + (c & 1) * STG_SIZE;
        const int k0 = c * KC;
#pragma unroll
        for (int it = 0; it < 4; it++) {
            cp_async16(sb + STG_A_HI + a_dst[it], a_hi[it] + k0);
            cp_async16(sb + STG_A_LO + a_dst[it], a_lo[it] + k0);
        }
        const __nv_bfloat16* wb = g_w2deq + (size_t)k0 * 65536;
#pragma unroll
        for (int it = 0; it < 4; it++)
            cp_async16(sb + b_dst[it], wb + b_src[it]);
    };

    float accg[4][4][4], accf[4][4][4];
#pragma unroll
    for (int a = 0; a < 4; a++)
#pragma unroll
        for (int b = 0; b < 4; b++)
#pragma unroll
            for (int c = 0; c < 4; c++) { accg[a][b][c] = 0.f; accf[a][b][c] = 0.f; }

    const int NCH = IDIM / KC;  // 8
    load_stage(0); CP_COMMIT();
#pragma unroll 1
    for (int c = 0; c < NCH; c++) {
        CP_WAIT(0);
        __syncthreads();
        if (c + 1 < NCH) { load_stage(c + 1); CP_COMMIT(); }
        warp_mma_chunk(smb + (c & 1) * STG_SIZE, warp_m, warp_n, lane, accg);
        if (c & 1) fold_group(accg, accf, sc_sm + (c >> 1) * 128, warp_n, lane);
    }

#pragma unroll
    for (int mf = 0; mf < 4; mf++) {
#pragma unroll
        for (int dd = 0; dd < 2; dd++) {
            int ml = warp_m * 64 + mf * 16 + (lane >> 2) + dd * 8;
            int gm = m0 + ml;
            if (gm < cnt) {
                float* op = out + (size_t)toks_sm[ml] * HDIM + h0;
#pragma unroll
                for (int nf = 0; nf < 4; nf++) {
                    int col = warp_n * 32 + nf * 8 + (lane & 3) * 2;
                    atomicAdd(op + col,     accf[mf][nf][dd * 2]);
                    atomicAdd(op + col + 1, accf[mf][nf][dd * 2 + 1]);
                }
            }
        }
    }
}

// ---------------- launch ----------------
extern "C" void kernel_launch(void* const* d_in, const int* in_sizes, int n_in,
                              void* d_out, int out_size) {
    const float* x   = (const float*)d_in[0];
    const float* gw  = (const float*)d_in[1];
    const int*   qw1 = (const int*)d_in[2];
    const int*   qz1 = (const int*)d_in[3];
    const float* sc1 = (const float*)d_in[4];
    const int*   qw2 = (const int*)d_in[5];
    const int*   qz2 = (const int*)d_in[6];
    const float* sc2 = (const float*)d_in[7];
    float* out = (float*)d_out;

    cudaFuncSetAttribute(gemm1_kernel, cudaFuncAttributeMaxDynamicSharedMemorySize, SMEM_TOTAL);
    cudaFuncSetAttribute(gemm2_kernel, cudaFuncAttributeMaxDynamicSharedMemorySize, SMEM_TOTAL);

    init_kernel<<<1, 64>>>();
    route_kernel<<<T_TOK, 256>>>(x, gw);
    dequant_kernel<<<(HDIM * 4096) / 256, 256>>>(qw1, qz1, 4096, 0);
    dequant_kernel<<<(IDIM * 8192) / 256, 256>>>(qw2, qz2, 8192, 1);
    xsplit_kernel<<<(T_TOK * HDIM / 4) / 256, 256>>>(x);
    prefix_kernel<<<1, 1>>>();
    fill_kernel<<<(NSLOTS + 255) / 256, 256>>>();
    cudaMemsetAsync(out, 0, (size_t)out_size * sizeof(float), 0);
    gemm1_kernel<<<dim3(IDIM / BN, T_TOK / BM, EDIM), 256, SMEM_TOTAL>>>(sc1);
    gemm2_kernel<<<dim3(HDIM / BN, T_TOK / BM, EDIM), 256, SMEM_TOTAL>>>(sc2, out);
}

// round 9
// speedup vs baseline: 1.7476x; 1.7476x over previous
#include <cuda_runtime.h>
#include <cuda_bf16.h>
#include <cstdint>
#include <cstddef>

#define T_TOK 2048
#define HDIM  1024
#define EDIM  64
#define NTOPK 8
#define IDIM  512

#define NSLOTS (T_TOK * NTOPK)      // 16384
#define PADSLOTS (NSLOTS + 128)

#define BM 128
#define BN 64
#define KC 64
#define NSTG 3

// per-stage smem layout (bytes)
#define STG_A    0                   // 128 x 64 bf16 = 16384
#define STG_B    16384               // 64 x 64 bf16 = 8192
#define STG_SIZE 24576
#define OFF_TOKS (NSTG * STG_SIZE)          // 73728: 128 ints
#define OFF_TWS  (OFF_TOKS + 512)           // 128 floats
#define OFF_SC   (OFF_TWS + 512)            // 512 floats
#define SMEM_TOTAL (OFF_SC + 2048)          // 76800

typedef unsigned int u32;

// ---------------- device scratch ----------------
__device__ int   g_count[EDIM];
__device__ int   g_offset[EDIM + 1];
__device__ int   g_fill[EDIM];
__device__ int   g_topk_idx[NSLOTS];
__device__ float g_topk_w[NSLOTS];
__device__ int   g_tok[PADSLOTS];
__device__ float g_tw[PADSLOTS];
__device__ __nv_bfloat16 g_xh[(size_t)T_TOK * HDIM];
__device__ __nv_bfloat16 g_hh[(size_t)PADSLOTS * IDIM];
__device__ __nv_bfloat16 g_w1deq[(size_t)HDIM * (EDIM * IDIM)];   // 64 MB
__device__ __nv_bfloat16 g_w2deq[(size_t)IDIM * (EDIM * HDIM)];   // 64 MB

__device__ __forceinline__ float silu_f(float v) { return v / (1.0f + __expf(-v)); }

__device__ __forceinline__ u32 smem_u32(const void* p) {
    u32 a;
    asm("{ .reg .u64 t; cvta.to.shared.u64 t, %1; cvt.u32.u64 %0, t; }" : "=r"(a) : "l"(p));
    return a;
}

__device__ __forceinline__ void cp_async16(u32 dst, const void* src) {
    asm volatile("cp.async.cg.shared.global [%0], [%1], 16;" :: "r"(dst), "l"(src));
}
#define CP_COMMIT() asm volatile("cp.async.commit_group;" ::: "memory")
#define CP_WAIT(n)  asm volatile("cp.async.wait_group %0;" :: "n"(n) : "memory")

#define LDMX4(r0, r1, r2, r3, addr) \
    asm volatile("ldmatrix.sync.aligned.m8n8.x4.shared.b16 {%0,%1,%2,%3}, [%4];" \
                 : "=r"(r0), "=r"(r1), "=r"(r2), "=r"(r3) : "r"(addr))

#define LDMX4T(r0, r1, r2, r3, addr) \
    asm volatile("ldmatrix.sync.aligned.m8n8.x4.trans.shared.b16 {%0,%1,%2,%3}, [%4];" \
                 : "=r"(r0), "=r"(r1), "=r"(r2), "=r"(r3) : "r"(addr))

#define MMA16816(d, a0, a1, a2, a3, b0, b1) \
    asm volatile("mma.sync.aligned.m16n8k16.row.col.f32.bf16.bf16.f32 " \
                 "{%0,%1,%2,%3}, {%4,%5,%6,%7}, {%8,%9}, {%0,%1,%2,%3};" \
                 : "+f"((d)[0]), "+f"((d)[1]), "+f"((d)[2]), "+f"((d)[3]) \
                 : "r"(a0), "r"(a1), "r"(a2), "r"(a3), "r"(b0), "r"(b1))

// ---------------- pre-processing kernels ----------------
__global__ __launch_bounds__(256) void dequant_kernel(const int* __restrict__ qw,
                                                      const int* __restrict__ qz,
                                                      int ncol8, int which) {
    __nv_bfloat16* __restrict__ wdeq = which ? g_w2deq : g_w1deq;
    int idx = blockIdx.x * 256 + threadIdx.x;
    int k = idx / ncol8, c8 = idx - k * ncol8;
    unsigned qv = (unsigned)qw[idx];
    unsigned zv = (unsigned)qz[(k >> 7) * ncol8 + c8];
    const int sh[8] = {0, 16, 4, 20, 8, 24, 12, 28};
    u32 o[4];
#pragma unroll
    for (int j = 0; j < 4; j++) {
        int d0 = (int)((qv >> sh[2 * j])     & 0xF) - (int)((zv >> sh[2 * j])     & 0xF);
        int d1 = (int)((qv >> sh[2 * j + 1]) & 0xF) - (int)((zv >> sh[2 * j + 1]) & 0xF);
        __nv_bfloat162 p = __floats2bfloat162_rn((float)d0, (float)d1);
        o[j] = *(u32*)&p;
    }
    *(uint4*)(wdeq + (size_t)idx * 8) = make_uint4(o[0], o[1], o[2], o[3]);
}

// x fp32 -> bf16
__global__ __launch_bounds__(256) void xcast_kernel(const float* __restrict__ x) {
    int i = blockIdx.x * 256 + threadIdx.x;
    float4 v = *(const float4*)(x + (size_t)i * 4);
    __nv_bfloat162 h01 = __floats2bfloat162_rn(v.x, v.y);
    __nv_bfloat162 h23 = __floats2bfloat162_rn(v.z, v.w);
    *(uint2*)(g_xh + (size_t)i * 4) = make_uint2(*(u32*)&h01, *(u32*)&h23);
}

// ---------------- routing kernels ----------------
__global__ void init_kernel() {
    int i = threadIdx.x;
    if (i < EDIM) g_count[i] = 0;
}

__global__ __launch_bounds__(256) void route_kernel(const float* __restrict__ x,
                                                    const float* __restrict__ gw) {
    int t = blockIdx.x;
    __shared__ float xs[HDIM];
    __shared__ float part[256];
    __shared__ float logit[EDIM];
    int tid = threadIdx.x;
    for (int i = tid; i < HDIM; i += 256) xs[i] = x[t * HDIM + i];
    __syncthreads();
    int e = tid & 63, q = tid >> 6;
    const float* w  = gw + e * HDIM + q * 256;
    const float* xq = xs + q * 256;
    float s = 0.f;
#pragma unroll 8
    for (int i = 0; i < 256; i++) s += xq[i] * w[i];
    part[tid] = s;
    __syncthreads();
    if (tid < 64)
        logit[tid] = part[tid] + part[tid + 64] + part[tid + 128] + part[tid + 192];
    __syncthreads();
    if (tid == 0) {
        float lv[NTOPK]; int li[NTOPK];
        for (int k = 0; k < NTOPK; k++) {
            float best = -1e30f; int bi = 0;
            for (int i = 0; i < EDIM; i++) { float v = logit[i]; if (v > best) { best = v; bi = i; } }
            lv[k] = best; li[k] = bi; logit[bi] = -1e30f;
        }
        float m = lv[0], sum = 0.f, wv[NTOPK];
        for (int k = 0; k < NTOPK; k++) { wv[k] = __expf(lv[k] - m); sum += wv[k]; }
        float inv = 1.f / sum;
        for (int k = 0; k < NTOPK; k++) {
            g_topk_idx[t * NTOPK + k] = li[k];
            g_topk_w[t * NTOPK + k]   = wv[k] * inv;
            atomicAdd(&g_count[li[k]], 1);
        }
    }
}

__global__ void prefix_kernel() {
    if (threadIdx.x == 0) {
        int acc = 0;
        for (int e = 0; e < EDIM; e++) { g_offset[e] = acc; acc += g_count[e]; g_fill[e] = 0; }
        g_offset[EDIM] = acc;
    }
}

__global__ void fill_kernel() {
    int i = blockIdx.x * blockDim.x + threadIdx.x;
    if (i >= NSLOTS) return;
    int e = g_topk_idx[i];
    int slot = atomicAdd(&g_fill[e], 1);
    int pos = g_offset[e] + slot;
    g_tok[pos] = i / NTOPK;
    g_tw[pos]  = g_topk_w[i];
}

// ---------------- warp MMA over one KC=64 stage (single bf16 pass) -----------
__device__ __forceinline__ void warp_mma_chunk(u32 sb, int warp_m, int warp_n,
                                               int lane, float accg[2][4][4]) {
#pragma unroll
    for (int ks = 0; ks < 4; ks++) {
        u32 b[4][2];
#pragma unroll
        for (int h = 0; h < 2; h++) {
            int tile = lane >> 3, row = lane & 7;
            int kk = ks * 16 + (tile & 1) * 8 + row;
            int nn = warp_n * 32 + h * 16 + (tile >> 1) * 8;
            u32 addr = sb + STG_B + (u32)(kk * 128 + (((nn >> 3) ^ (kk & 7)) << 4));
            LDMX4T(b[h * 2][0], b[h * 2][1], b[h * 2 + 1][0], b[h * 2 + 1][1], addr);
        }
#pragma unroll
        for (int mf = 0; mf < 2; mf++) {
            int mm = warp_m * 32 + mf * 16 + (lane & 15);
            int ch = ks * 2 + (lane >> 4);
            u32 addr = sb + STG_A + (u32)(mm * 128 + ((ch ^ (mm & 7)) << 4));
            u32 a0, a1, a2, a3;
            LDMX4(a0, a1, a2, a3, addr);
            MMA16816(accg[mf][0], a0, a1, a2, a3, b[0][0], b[0][1]);
            MMA16816(accg[mf][1], a0, a1, a2, a3, b[1][0], b[1][1]);
            MMA16816(accg[mf][2], a0, a1, a2, a3, b[2][0], b[2][1]);
            MMA16816(accg[mf][3], a0, a1, a2, a3, b[3][0], b[3][1]);
        }
    }
}

__device__ __forceinline__ void fold_group(float accg[2][4][4], float accf[2][4][4],
                                           const float* sc_g, int warp_n, int lane) {
#pragma unroll
    for (int nf = 0; nf < 4; nf++) {
        int col = warp_n * 32 + nf * 8 + (lane & 3) * 2;
        float s0 = sc_g[col], s1 = sc_g[col + 1];
#pragma unroll
        for (int mf = 0; mf < 2; mf++) {
            accf[mf][nf][0] += s0 * accg[mf][nf][0];
            accf[mf][nf][1] += s1 * accg[mf][nf][1];
            accf[mf][nf][2] += s0 * accg[mf][nf][2];
            accf[mf][nf][3] += s1 * accg[mf][nf][3];
            accg[mf][nf][0] = 0.f; accg[mf][nf][1] = 0.f;
            accg[mf][nf][2] = 0.f; accg[mf][nf][3] = 0.f;
        }
    }
}

// ---------------- GEMM1 ----------------
__global__ __launch_bounds__(256, 2) void gemm1_kernel(const float* __restrict__ sc1) {
    const int e    = blockIdx.z;
    const int base = g_offset[e];
    const int cnt  = g_offset[e + 1] - base;
    const int m0   = blockIdx.y * BM;
    if (m0 >= cnt) return;
    const int i0 = blockIdx.x * BN;

    extern __shared__ char sm[];
    const u32 smb = smem_u32(sm);
    int*   toks_sm = (int*)(sm + OFF_TOKS);
    float* tws_sm  = (float*)(sm + OFF_TWS);
    float* sc_sm   = (float*)(sm + OFF_SC);

    const int tid  = threadIdx.x;
    const int wid  = tid >> 5;
    const int lane = tid & 31;
    const int warp_m = wid & 3;
    const int warp_n = wid >> 2;

    if (tid < 128) {
        toks_sm[tid] = g_tok[base + m0 + tid];
        tws_sm[tid]  = g_tw[base + m0 + tid];
    }
#pragma unroll
    for (int it = 0; it < 2; it++) {
        int idx = it * 256 + tid;
        sc_sm[idx] = sc1[(idx >> 6) * 32768 + e * IDIM + i0 + (idx & 63)];
    }
    __syncthreads();

    // loaders: A 4 cp/thread, B 2 cp/thread
    const __nv_bfloat16* a_src[4];
    u32 a_dst[4];
#pragma unroll
    for (int it = 0; it < 4; it++) {
        int idx = it * 256 + tid;
        int m = idx >> 3, cc = idx & 7;
        a_src[it] = g_xh + (size_t)toks_sm[m] * HDIM + cc * 8;
        a_dst[it] = (u32)(m * 128 + ((cc ^ (m & 7)) << 4));
    }
    u32 b_dst[2]; size_t b_src[2];
    const int ncolbase = e * IDIM + i0;
#pragma unroll
    for (int it = 0; it < 2; it++) {
        int idx = it * 256 + tid;
        int kr = idx >> 3, cc = idx & 7;
        b_dst[it] = (u32)(STG_B + kr * 128 + ((cc ^ (kr & 7)) << 4));
        b_src[it] = (size_t)kr * 32768 + ncolbase + cc * 8;
    }

    auto load_stage = [&](int c) {
        u32 sb = smb + (c % NSTG) * STG_SIZE;
        const int k0 = c * KC;
#pragma unroll
        for (int it = 0; it < 4; it++)
            cp_async16(sb + STG_A + a_dst[it], a_src[it] + k0);
        const __nv_bfloat16* wb = g_w1deq + (size_t)k0 * 32768;
#pragma unroll
        for (int it = 0; it < 2; it++)
            cp_async16(sb + b_dst[it], wb + b_src[it]);
    };

    float accg[2][4][4], accf[2][4][4];
#pragma unroll
    for (int a = 0; a < 2; a++)
#pragma unroll
        for (int b = 0; b < 4; b++)
#pragma unroll
            for (int c = 0; c < 4; c++) { accg[a][b][c] = 0.f; accf[a][b][c] = 0.f; }

    const int NCH = HDIM / KC;  // 16
    load_stage(0); CP_COMMIT();
    load_stage(1); CP_COMMIT();
#pragma unroll 1
    for (int c = 0; c < NCH; c++) {
        if (c == NCH - 1) { CP_WAIT(0); } else { CP_WAIT(1); }
        __syncthreads();
        if (c + 2 < NCH) { load_stage(c + 2); CP_COMMIT(); }
        warp_mma_chunk(smb + (c % NSTG) * STG_SIZE, warp_m, warp_n, lane, accg);
        if (c & 1) fold_group(accg, accf, sc_sm + (c >> 1) * 64, warp_n, lane);
    }

    // epilogue: silu * tw -> bf16
#pragma unroll
    for (int mf = 0; mf < 2; mf++) {
#pragma unroll
        for (int dd = 0; dd < 2; dd++) {
            int ml = warp_m * 32 + mf * 16 + (lane >> 2) + dd * 8;
            int gm = m0 + ml;
            if (gm < cnt) {
                float tw = tws_sm[ml];
                __nv_bfloat16* oph = g_hh + (size_t)(base + gm) * IDIM + i0;
#pragma unroll
                for (int nf = 0; nf < 4; nf++) {
                    int col = warp_n * 32 + nf * 8 + (lane & 3) * 2;
                    float v0 = silu_f(accf[mf][nf][dd * 2]) * tw;
                    float v1 = silu_f(accf[mf][nf][dd * 2 + 1]) * tw;
                    __nv_bfloat162 h = __floats2bfloat162_rn(v0, v1);
                    *(u32*)(oph + col) = *(u32*)&h;
                }
            }
        }
    }
}

// ---------------- GEMM2 ----------------
__global__ __launch_bounds__(256, 2) void gemm2_kernel(const float* __restrict__ sc2,
                                                       float* __restrict__ out) {
    const int e    = blockIdx.z;
    const int base = g_offset[e];
    const int cnt  = g_offset[e + 1] - base;
    const int m0   = blockIdx.y * BM;
    if (m0 >= cnt) return;
    const int h0 = blockIdx.x * BN;

    extern __shared__ char sm[];
    const u32 smb = smem_u32(sm);
    int*   toks_sm = (int*)(sm + OFF_TOKS);
    float* sc_sm   = (float*)(sm + OFF_SC);

    const int tid  = threadIdx.x;
    const int wid  = tid >> 5;
    const int lane = tid & 31;
    const int warp_m = wid & 3;
    const int warp_n = wid >> 2;

    if (tid < 128) toks_sm[tid] = g_tok[base + m0 + tid];
    sc_sm[tid] = sc2[(tid >> 6) * 65536 + e * HDIM + h0 + (tid & 63)];
    __syncthreads();

    const __nv_bfloat16* a_src[4];
    u32 a_dst[4];
#pragma unroll
    for (int it = 0; it < 4; it++) {
        int idx = it * 256 + tid;
        int m = idx >> 3, cc = idx & 7;
        a_src[it] = g_hh + (size_t)(base + m0 + m) * IDIM + cc * 8;
        a_dst[it] = (u32)(m * 128 + ((cc ^ (m & 7)) << 4));
    }
    u32 b_dst[2]; size_t b_src[2];
    const int ncolbase = e * HDIM + h0;
#pragma unroll
    for (int it = 0; it < 2; it++) {
        int idx = it * 256 + tid;
        int kr = idx >> 3, cc = idx & 7;
        b_dst[it] = (u32)(STG_B + kr * 128 + ((cc ^ (kr & 7)) << 4));
        b_src[it] = (size_t)kr * 65536 + ncolbase + cc * 8;
    }

    auto load_stage = [&](int c) {
        u32 sb = smb + (c % NSTG) * STG_SIZE;
        const int k0 = c * KC;
#pragma unroll
        for (int it = 0; it < 4; it++)
            cp_async16(sb + STG_A + a_dst[it], a_src[it] + k0);
        const __nv_bfloat16* wb = g_w2deq + (size_t)k0 * 65536;
#pragma unroll
        for (int it = 0; it < 2; it++)
            cp_async16(sb + b_dst[it], wb + b_src[it]);
    };

    float accg[2][4][4], accf[2][4][4];
#pragma unroll
    for (int a = 0; a < 2; a++)
#pragma unroll
        for (int b = 0; b < 4; b++)
#pragma unroll
            for (int c = 0; c < 4; c++) { accg[a][b][c] = 0.f; accf[a][b][c] = 0.f; }

    const int NCH = IDIM / KC;  // 8
    load_stage(0); CP_COMMIT();
    load_stage(1); CP_COMMIT();
#pragma unroll 1
    for (int c = 0; c < NCH; c++) {
        if (c == NCH - 1) { CP_WAIT(0); } else { CP_WAIT(1); }
        __syncthreads();
        if (c + 2 < NCH) { load_stage(c + 2); CP_COMMIT(); }
        warp_mma_chunk(smb + (c % NSTG) * STG_SIZE, warp_m, warp_n, lane, accg);
        if (c & 1) fold_group(accg, accf, sc_sm + (c >> 1) * 64, warp_n, lane);
    }

#pragma unroll
    for (int mf = 0; mf < 2; mf++) {
#pragma unroll
        for (int dd = 0; dd < 2; dd++) {
            int ml = warp_m * 32 + mf * 16 + (lane >> 2) + dd * 8;
            int gm = m0 + ml;
            if (gm < cnt) {
                float* op = out + (size_t)toks_sm[ml] * HDIM + h0;
#pragma unroll
                for (int nf = 0; nf < 4; nf++) {
                    int col = warp_n * 32 + nf * 8 + (lane & 3) * 2;
                    atomicAdd(op + col,     accf[mf][nf][dd * 2]);
                    atomicAdd(op + col + 1, accf[mf][nf][dd * 2 + 1]);
                }
            }
        }
    }
}

// ---------------- launch ----------------
extern "C" void kernel_launch(void* const* d_in, const int* in_sizes, int n_in,
                              void* d_out, int out_size) {
    const float* x   = (const float*)d_in[0];
    const float* gw  = (const float*)d_in[1];
    const int*   qw1 = (const int*)d_in[2];
    const int*   qz1 = (const int*)d_in[3];
    const float* sc1 = (const float*)d_in[4];
    const int*   qw2 = (const int*)d_in[5];
    const int*   qz2 = (const int*)d_in[6];
    const float* sc2 = (const float*)d_in[7];
    float* out = (float*)d_out;

    cudaFuncSetAttribute(gemm1_kernel, cudaFuncAttributeMaxDynamicSharedMemorySize, SMEM_TOTAL);
    cudaFuncSetAttribute(gemm2_kernel, cudaFuncAttributeMaxDynamicSharedMemorySize, SMEM_TOTAL);

    init_kernel<<<1, 64>>>();
    route_kernel<<<T_TOK, 256>>>(x, gw);
    dequant_kernel<<<(HDIM * 4096) / 256, 256>>>(qw1, qz1, 4096, 0);
    dequant_kernel<<<(IDIM * 8192) / 256, 256>>>(qw2, qz2, 8192, 1);
    xcast_kernel<<<(T_TOK * HDIM / 4) / 256, 256>>>(x);
    prefix_kernel<<<1, 1>>>();
    fill_kernel<<<(NSLOTS + 255) / 256, 256>>>();
    cudaMemsetAsync(out, 0, (size_t)out_size * sizeof(float), 0);
    gemm1_kernel<<<dim3(IDIM / BN, T_TOK / BM, EDIM), 256, SMEM_TOTAL>>>(sc1);
    gemm2_kernel<<<dim3(HDIM / BN, T_TOK / BM, EDIM), 256, SMEM_TOTAL>>>(sc2, out);
}